// round 14
// baseline (speedup 1.0000x reference)
#include <cuda_runtime.h>
#include <cstdint>

#define NNODES  50000
#define NPAD    50048      // 391 * 128
#define NEDGE   500000
#define DIM     128
#define DIM2    256
#define NLAYERS 5
#define NGRAPH  128

// ---------------- scratch (static device globals; zero-initialized) ----------------
__device__ float g_h [(size_t)NPAD * DIM];
__device__ float g_z [(size_t)NPAD * DIM];
__device__ float g_z1[(size_t)NPAD * DIM2];
__device__ float g_sum1[DIM2], g_sq1[DIM2];
__device__ float g_sum2[DIM ], g_sq2[DIM ];
__device__ int   g_cnt1, g_cnt2;
// pre-transposed [N][K], bf16-split (hi/lo), bf16x2-packed weights
__device__ uint32_t g_w1h[NLAYERS * DIM2 * (DIM / 2)];
__device__ uint32_t g_w1l[NLAYERS * DIM2 * (DIM / 2)];
__device__ uint32_t g_w2h[NLAYERS * DIM * (DIM2 / 2)];
__device__ uint32_t g_w2l[NLAYERS * DIM * (DIM2 / 2)];

// ---------------- PTX helpers (baseline features only) ----------------
__device__ __forceinline__ void red_add_v4(float* p, float4 v) {
    asm volatile("red.global.add.v4.f32 [%0], {%1, %2, %3, %4};"
                 :: "l"(p), "f"(v.x), "f"(v.y), "f"(v.z), "f"(v.w) : "memory");
}
__device__ __forceinline__ uint32_t bfpack(float v0, float v1) {
    uint32_t r;
    asm("cvt.rn.bf16x2.f32 %0, %1, %2;" : "=r"(r) : "f"(v1), "f"(v0));
    return r;
}
__device__ __forceinline__ uint32_t smem_u32(const void* p) {
    uint32_t a;
    asm("{ .reg .u64 t; cvta.to.shared.u64 t, %1; cvt.u32.u64 %0, t; }" : "=r"(a) : "l"(p));
    return a;
}
__device__ __forceinline__ void ldsm4(uint32_t r[4], uint32_t addr) {
    asm volatile("ldmatrix.sync.aligned.m8n8.x4.shared.b16 {%0,%1,%2,%3}, [%4];"
                 : "=r"(r[0]), "=r"(r[1]), "=r"(r[2]), "=r"(r[3]) : "r"(addr));
}
__device__ __forceinline__ void mma_bf16(float c[4], const uint32_t a[4],
                                         uint32_t b0, uint32_t b1) {
    asm volatile("mma.sync.aligned.m16n8k16.row.col.f32.bf16.bf16.f32 "
                 "{%0,%1,%2,%3}, {%4,%5,%6,%7}, {%8,%9}, {%0,%1,%2,%3};"
                 : "+f"(c[0]), "+f"(c[1]), "+f"(c[2]), "+f"(c[3])
                 : "r"(a[0]), "r"(a[1]), "r"(a[2]), "r"(a[3]), "r"(b0), "r"(b1));
}

// ---------------- layer-0 init ----------------
__global__ void k_init(const int* __restrict__ x, const float* __restrict__ atom_emb,
                       float* __restrict__ out) {
    int i = blockIdx.x * blockDim.x + threadIdx.x;
    if (i < NGRAPH * DIM) out[i] = 0.f;
    if (i >= NNODES * 32) return;
    int n = i >> 5, c = (i & 31) * 4;
    int a = __ldg(x + n);
    float4 v = *(const float4*)(atom_emb + (size_t)a * DIM + c);
    *(float4*)(g_h + (size_t)n * DIM + c) = v;
    *(float4*)(g_z + (size_t)n * DIM + c) = v;
}

// ---------------- weight prep: transpose [N][K], bf16 hi/lo split, bf16x2 pack ----------------
__global__ void k_prep(const float* __restrict__ W1, const float* __restrict__ W2) {
    const int T1 = NLAYERS * DIM2 * (DIM / 2);
    const int T2 = NLAYERS * DIM * (DIM2 / 2);
    int i = blockIdx.x * blockDim.x + threadIdx.x;
    if (i < T1) {
        int l = i / (DIM2 * (DIM / 2)), r = i % (DIM2 * (DIM / 2));
        int n = r / (DIM / 2), w = r % (DIM / 2);
        const float* base = W1 + (size_t)l * DIM * DIM2;
        float v0 = base[(size_t)(2 * w) * DIM2 + n];
        float v1 = base[(size_t)(2 * w + 1) * DIM2 + n];
        uint32_t hp = bfpack(v0, v1);
        float f0 = __uint_as_float(hp << 16);
        float f1 = __uint_as_float(hp & 0xffff0000u);
        g_w1h[i] = hp;
        g_w1l[i] = bfpack(v0 - f0, v1 - f1);
    } else if (i < T1 + T2) {
        int j = i - T1;
        int l = j / (DIM * (DIM2 / 2)), r = j % (DIM * (DIM2 / 2));
        int n = r / (DIM2 / 2), w = r % (DIM2 / 2);
        const float* base = W2 + (size_t)l * DIM2 * DIM;
        float v0 = base[(size_t)(2 * w) * DIM + n];
        float v1 = base[(size_t)(2 * w + 1) * DIM + n];
        uint32_t hp = bfpack(v0, v1);
        float f0 = __uint_as_float(hp << 16);
        float f1 = __uint_as_float(hp & 0xffff0000u);
        g_w2h[j] = hp;
        g_w2l[j] = bfpack(v0 - f0, v1 - f1);
    }
}

// ---------------- message passing (8 edges/warp, MLP) ----------------
__global__ void k_scatter(const int* __restrict__ src, const int* __restrict__ dst,
                          const int* __restrict__ eattr, const float* __restrict__ bond_emb) {
    const int wid  = threadIdx.x >> 5;
    const int lane = threadIdx.x & 31;
    const int e0 = blockIdx.x * 64 + wid * 8;
    const int c4 = lane * 4;

    if (e0 + 8 <= NEDGE) {
        int s[8], d[8], a[8];
        #pragma unroll
        for (int j = 0; j < 8; j++) {
            s[j] = __ldg(src + e0 + j);
            d[j] = __ldg(dst + e0 + j);
            a[j] = __ldg(eattr + e0 + j);
        }
        float4 hv[8], ev[8];
        #pragma unroll
        for (int j = 0; j < 8; j++)
            hv[j] = *(const float4*)(g_h + (size_t)s[j] * DIM + c4);
        #pragma unroll
        for (int j = 0; j < 8; j++)
            ev[j] = *(const float4*)(bond_emb + (size_t)a[j] * DIM + c4);
        #pragma unroll
        for (int j = 0; j < 8; j++) {
            float4 m;
            m.x = fmaxf(hv[j].x + ev[j].x, 0.f);
            m.y = fmaxf(hv[j].y + ev[j].y, 0.f);
            m.z = fmaxf(hv[j].z + ev[j].z, 0.f);
            m.w = fmaxf(hv[j].w + ev[j].w, 0.f);
            red_add_v4(g_z + (size_t)d[j] * DIM + c4, m);
        }
    } else {
        for (int j = 0; j < 8; j++) {
            int e = e0 + j;
            if (e >= NEDGE) break;
            int s = __ldg(src + e), d = __ldg(dst + e), a = __ldg(eattr + e);
            float4 hv = *(const float4*)(g_h + (size_t)s * DIM + c4);
            float4 ev = *(const float4*)(bond_emb + (size_t)a * DIM + c4);
            float4 m;
            m.x = fmaxf(hv.x + ev.x, 0.f);
            m.y = fmaxf(hv.y + ev.y, 0.f);
            m.z = fmaxf(hv.z + ev.z, 0.f);
            m.w = fmaxf(hv.w + ev.w, 0.f);
            red_add_v4(g_z + (size_t)d * DIM + c4, m);
        }
    }
}

// ---------------- GEMM via 3x BF16-split mma.sync: C = A @ Wt^T + bias ----------------
// CTA tile 128x64, 8 warps (4m x 2n), warp tile 32x32 = 2x4 m16n8k16 fragments.
// Small acc (32 regs) + hoisted fragments fit <=84 regs -> 3 CTAs/SM (24 warps).
// K staged in 32-col chunks (hi/lo bf16x2, 16 words/row, row stride 20 words).
// 3 products: AhBh + AhBl + AlBh. AFF: BN affine inline once per CTA; last CTA
// re-zeroes stats (replay safe).
template<int K, int NC, bool AFF>
__global__ void __launch_bounds__(256, 3)
k_gemm(const float* __restrict__ A,
       const uint32_t* __restrict__ Bh, const uint32_t* __restrict__ Bl,
       const float* __restrict__ bias,
       const float* __restrict__ sumA, const float* __restrict__ sqA,
       const float* __restrict__ gammaA, const float* __restrict__ betaA,
       int* __restrict__ cntA, int nCTA,
       float* __restrict__ C, float* __restrict__ gsum, float* __restrict__ gsq) {
    __shared__ uint32_t sAh[128 * 20], sAl[128 * 20];
    __shared__ uint32_t sBh[64 * 20],  sBl[64 * 20];
    __shared__ float sbias[64];
    __shared__ float saff[2 * K];
    __shared__ int s_last;

    const int tid  = threadIdx.x;
    const int lane = tid & 31, wid = tid >> 5;
    const int g = lane >> 2, tg = lane & 3;
    const int wm = wid >> 1, wn = wid & 1;           // 4m x 2n warp grid
    const int mrow = wm * 32, ncol = wn * 32;
    const int bm0 = blockIdx.x * 128, bn0 = blockIdx.y * 64;

    if (tid < 64) sbias[tid] = bias[bn0 + tid];

    if (AFF) {
        if (tid < K) {
            const float invn = 1.0f / (float)NNODES;
            float mu  = sumA[tid] * invn;
            float var = fmaxf(sqA[tid] * invn - mu * mu, 0.f);
            float sc  = rsqrtf(var + 1e-5f) * gammaA[tid];
            saff[tid]     = sc;
            saff[K + tid] = betaA[tid] - mu * sc;
        }
        __syncthreads();
        if (tid == 0) {
            __threadfence();
            int old = atomicAdd(cntA, 1);
            s_last = (old == nCTA - 1);
        }
        __syncthreads();
        if (s_last) {
            if (tid < K) { ((float*)sumA)[tid] = 0.f; ((float*)sqA)[tid] = 0.f; }
            if (tid == 0) *cntA = 0;
        }
    }

    float acc[2][4][4];
    #pragma unroll
    for (int i = 0; i < 2; i++)
        #pragma unroll
        for (int j = 0; j < 4; j++)
            #pragma unroll
            for (int r = 0; r < 4; r++) acc[i][j][r] = 0.f;

    // staging: A: 2 threads/row x 128 rows (all 256). B: tid<128, 2 threads/row x 64 rows.
    const int s_row  = tid >> 1;
    const int s_half = tid & 1;
    const float*    Ab  = A  + (size_t)(bm0 + s_row) * K + s_half * 16;
    const int b_row  = (tid & 127) >> 1;
    const int b_half = tid & 1;
    const uint32_t* Bhb = Bh + (size_t)(bn0 + b_row) * (K / 2) + b_half * 8;
    const uint32_t* Blb = Bl + (size_t)(bn0 + b_row) * (K / 2) + b_half * 8;
    const int a_off = s_row * 20 + s_half * 8;
    const int b_off = b_row * 20 + b_half * 8;

    const uint32_t aBh = smem_u32(sAh), aBl = smem_u32(sAl);
    const uint32_t bBh = smem_u32(sBh), bBl = smem_u32(sBl);

    #pragma unroll 1
    for (int ch = 0; ch < K / 32; ch++) {
        const int kc = ch * 32;
        __syncthreads();                      // previous chunk's fragment reads done
        // ---- stage A: load fp32, (affine+relu), split hi/lo bf16, pack ----
        {
            float v[16];
            *(float4*)&v[0]  = *(const float4*)(Ab + kc);
            *(float4*)&v[4]  = *(const float4*)(Ab + kc + 4);
            *(float4*)&v[8]  = *(const float4*)(Ab + kc + 8);
            *(float4*)&v[12] = *(const float4*)(Ab + kc + 12);
            if (AFF) {
                const float* sc = saff + kc + s_half * 16;
                const float* sh = sc + K;
                #pragma unroll
                for (int j = 0; j < 16; j++)
                    v[j] = fmaxf(fmaf(v[j], sc[j], sh[j]), 0.f);
            }
            uint32_t hw[8], lw[8];
            #pragma unroll
            for (int p = 0; p < 8; p++) {
                float v0 = v[2 * p], v1 = v[2 * p + 1];
                uint32_t hp = bfpack(v0, v1);
                float f0 = __uint_as_float(hp << 16);
                float f1 = __uint_as_float(hp & 0xffff0000u);
                hw[p] = hp;
                lw[p] = bfpack(v0 - f0, v1 - f1);
            }
            *(uint4*)(sAh + a_off)     = *(uint4*)&hw[0];
            *(uint4*)(sAh + a_off + 4) = *(uint4*)&hw[4];
            *(uint4*)(sAl + a_off)     = *(uint4*)&lw[0];
            *(uint4*)(sAl + a_off + 4) = *(uint4*)&lw[4];
        }
        // ---- stage B (tid < 128): copy pre-split weights ----
        if (tid < 128) {
            uint4 h0 = *(const uint4*)(Bhb + kc / 2);
            uint4 h1 = *(const uint4*)(Bhb + kc / 2 + 4);
            uint4 l0 = *(const uint4*)(Blb + kc / 2);
            uint4 l1 = *(const uint4*)(Blb + kc / 2 + 4);
            *(uint4*)(sBh + b_off)     = h0;
            *(uint4*)(sBh + b_off + 4) = h1;
            *(uint4*)(sBl + b_off)     = l0;
            *(uint4*)(sBl + b_off + 4) = l1;
        }
        __syncthreads();

        // ---- 2 k16 steps of MMA ----
        #pragma unroll
        for (int k16 = 0; k16 < 2; k16++) {
            const uint32_t lrow = (uint32_t)((lane & 7) + (((lane >> 3) & 1) << 3));
            const uint32_t lcol = (uint32_t)(((lane >> 4) & 1) * 4 + k16 * 8);
            uint32_t bh[2][4], bl[2][4];
            #pragma unroll
            for (int jp = 0; jp < 2; jp++) {
                uint32_t ba = ((uint32_t)(ncol + jp * 16) + lrow) * 80u + lcol * 4u;
                ldsm4(bh[jp], bBh + ba);
                ldsm4(bl[jp], bBl + ba);
            }
            #pragma unroll
            for (int i = 0; i < 2; i++) {
                uint32_t ra = ((uint32_t)(mrow + i * 16) + lrow) * 80u + lcol * 4u;
                uint32_t ah[4], al[4];
                ldsm4(ah, aBh + ra);
                ldsm4(al, aBl + ra);
                #pragma unroll
                for (int j = 0; j < 4; j++) {
                    const int jp = j >> 1, od = j & 1;
                    mma_bf16(acc[i][j], ah, bh[jp][od], bh[jp][2 + od]);
                    mma_bf16(acc[i][j], ah, bl[jp][od], bl[jp][2 + od]);
                    mma_bf16(acc[i][j], al, bh[jp][od], bh[jp][2 + od]);
                }
            }
        }
    }

    // ---- epilogue: bias, store, masked column stats ----
    float ps[4][2], pq[4][2];
    #pragma unroll
    for (int j = 0; j < 4; j++) { ps[j][0] = ps[j][1] = pq[j][0] = pq[j][1] = 0.f; }

    #pragma unroll
    for (int i = 0; i < 2; i++) {
        int r0 = bm0 + mrow + i * 16 + g;
        int r1 = r0 + 8;
        #pragma unroll
        for (int j = 0; j < 4; j++) {
            int lc = ncol + j * 8 + 2 * tg;
            float b0 = sbias[lc], b1 = sbias[lc + 1];
            float v0 = acc[i][j][0] + b0, v1 = acc[i][j][1] + b1;
            float v2 = acc[i][j][2] + b0, v3 = acc[i][j][3] + b1;
            *(float2*)(C + (size_t)r0 * NC + bn0 + lc) = make_float2(v0, v1);
            *(float2*)(C + (size_t)r1 * NC + bn0 + lc) = make_float2(v2, v3);
            if (r0 < NNODES) {
                ps[j][0] += v0; pq[j][0] += v0 * v0;
                ps[j][1] += v1; pq[j][1] += v1 * v1;
            }
            if (r1 < NNODES) {
                ps[j][0] += v2; pq[j][0] += v2 * v2;
                ps[j][1] += v3; pq[j][1] += v3 * v3;
            }
        }
    }
    #pragma unroll
    for (int j = 0; j < 4; j++)
        #pragma unroll
        for (int t2 = 0; t2 < 2; t2++) {
            float s = ps[j][t2], q = pq[j][t2];
            s += __shfl_xor_sync(0xFFFFFFFFu, s, 4);
            q += __shfl_xor_sync(0xFFFFFFFFu, q, 4);
            s += __shfl_xor_sync(0xFFFFFFFFu, s, 8);
            q += __shfl_xor_sync(0xFFFFFFFFu, q, 8);
            s += __shfl_xor_sync(0xFFFFFFFFu, s, 16);
            q += __shfl_xor_sync(0xFFFFFFFFu, q, 16);
            if (lane < 4) {
                int col = bn0 + ncol + j * 8 + 2 * tg + t2;
                atomicAdd(gsum + col, s);
                atomicAdd(gsq  + col, q);
            }
        }
}

// ---------------- apply BN2 (+optional ReLU): h = bn(z2); z = h ----------------
__global__ void k_bnapply(const float* __restrict__ gamma, const float* __restrict__ beta,
                          int relu, int nBLK) {
    __shared__ float saff[2 * DIM];
    __shared__ int s_last;
    int tid = threadIdx.x;
    if (tid < DIM) {
        const float invn = 1.0f / (float)NNODES;
        float mu  = g_sum2[tid] * invn;
        float var = fmaxf(g_sq2[tid] * invn - mu * mu, 0.f);
        float sc  = rsqrtf(var + 1e-5f) * gamma[tid];
        saff[tid]       = sc;
        saff[DIM + tid] = beta[tid] - mu * sc;
    }
    __syncthreads();
    if (tid == 0) {
        __threadfence();
        int old = atomicAdd(&g_cnt2, 1);
        s_last = (old == nBLK - 1);
    }
    __syncthreads();
    if (s_last) {
        if (tid < DIM) { g_sum2[tid] = 0.f; g_sq2[tid] = 0.f; }
        if (tid == 0) g_cnt2 = 0;
    }

    int i = blockIdx.x * blockDim.x + tid;
    if (i >= NNODES * 32) return;
    int n = i >> 5, c = (i & 31) * 4;
    float4 v  = *(const float4*)(g_z + (size_t)n * DIM + c);
    float4 sc = *(const float4*)(saff + c);
    float4 sh = *(const float4*)(saff + DIM + c);
    v.x = fmaf(v.x, sc.x, sh.x);
    v.y = fmaf(v.y, sc.y, sh.y);
    v.z = fmaf(v.z, sc.z, sh.z);
    v.w = fmaf(v.w, sc.w, sh.w);
    if (relu) {
        v.x = fmaxf(v.x, 0.f); v.y = fmaxf(v.y, 0.f);
        v.z = fmaxf(v.z, 0.f); v.w = fmaxf(v.w, 0.f);
    }
    *(float4*)(g_h + (size_t)n * DIM + c) = v;
    *(float4*)(g_z + (size_t)n * DIM + c) = v;
}

__global__ void k_pool(const int* __restrict__ batch, float* __restrict__ out) {
    int i = blockIdx.x * blockDim.x + threadIdx.x;
    if (i >= NNODES * 32) return;
    int n = i >> 5, c = (i & 31) * 4;
    float4 v = *(const float4*)(g_h + (size_t)n * DIM + c);
    *(float4*)(out + (size_t)NGRAPH * DIM + (size_t)n * DIM + c) = v;
    int b = __ldg(batch + n);
    red_add_v4(out + (size_t)b * DIM + c, v);
}

// ---------------- launch ----------------
extern "C" void kernel_launch(void* const* d_in, const int* in_sizes, int n_in,
                              void* d_out, int out_size) {
    const int*   batch    = (const int*)  d_in[0];
    const int*   x        = (const int*)  d_in[1];
    const int*   eidx     = (const int*)  d_in[2];
    const int*   eattr    = (const int*)  d_in[3];
    const float* atom_emb = (const float*)d_in[4];
    const float* bond_emb = (const float*)d_in[5];
    const float* W1       = (const float*)d_in[6];
    const float* b1       = (const float*)d_in[7];
    const float* g1       = (const float*)d_in[8];
    const float* be1      = (const float*)d_in[9];
    const float* W2       = (const float*)d_in[10];
    const float* b2       = (const float*)d_in[11];
    const float* gbn      = (const float*)d_in[12];
    const float* bbn      = (const float*)d_in[13];
    float* out = (float*)d_out;

    float *p_z, *p_z1, *p_sum1, *p_sq1, *p_sum2, *p_sq2;
    int *p_cnt1;
    uint32_t *p_w1h, *p_w1l, *p_w2h, *p_w2l;
    cudaGetSymbolAddress((void**)&p_z,    g_z);
    cudaGetSymbolAddress((void**)&p_z1,   g_z1);
    cudaGetSymbolAddress((void**)&p_sum1, g_sum1);
    cudaGetSymbolAddress((void**)&p_sq1,  g_sq1);
    cudaGetSymbolAddress((void**)&p_sum2, g_sum2);
    cudaGetSymbolAddress((void**)&p_sq2,  g_sq2);
    cudaGetSymbolAddress((void**)&p_cnt1, g_cnt1);
    cudaGetSymbolAddress((void**)&p_w1h,  g_w1h);
    cudaGetSymbolAddress((void**)&p_w1l,  g_w1l);
    cudaGetSymbolAddress((void**)&p_w2h,  g_w2h);
    cudaGetSymbolAddress((void**)&p_w2l,  g_w2l);

    const int* src = eidx;
    const int* dst = eidx + NEDGE;
    const int ELEM_GRID = (NNODES * 32 + 255) / 256;
    const int G2_CTAS   = (NPAD / 128) * (DIM / 64);   // 782
    const int PREP_TOT  = NLAYERS * DIM2 * (DIM / 2) + NLAYERS * DIM * (DIM2 / 2);

    k_init<<<ELEM_GRID, 256>>>(x, atom_emb, out);
    k_prep<<<(PREP_TOT + 255) / 256, 256>>>(W1, W2);

    for (int i = 0; i < NLAYERS; i++) {
        k_scatter<<<(NEDGE + 63) / 64, 256>>>(src, dst, eattr, bond_emb);
        k_gemm<DIM, DIM2, false><<<dim3(NPAD / 128, DIM2 / 64), 256>>>(
            p_z, p_w1h + (size_t)i * DIM2 * (DIM / 2), p_w1l + (size_t)i * DIM2 * (DIM / 2),
            b1 + (size_t)i * DIM2,
            nullptr, nullptr, nullptr, nullptr, nullptr, 0,
            p_z1, p_sum1, p_sq1);
        k_gemm<DIM2, DIM, true><<<dim3(NPAD / 128, DIM / 64), 256>>>(
            p_z1, p_w2h + (size_t)i * DIM * (DIM2 / 2), p_w2l + (size_t)i * DIM * (DIM2 / 2),
            b2 + (size_t)i * DIM,
            p_sum1, p_sq1, g1 + (size_t)i * DIM2, be1 + (size_t)i * DIM2,
            p_cnt1, G2_CTAS,
            p_z, p_sum2, p_sq2);
        k_bnapply<<<ELEM_GRID, 256>>>(gbn + (size_t)i * DIM, bbn + (size_t)i * DIM,
                                      i < NLAYERS - 1 ? 1 : 0, ELEM_GRID);
    }

    k_pool<<<ELEM_GRID, 256>>>(batch, out);
}

// round 15
// speedup vs baseline: 1.3406x; 1.3406x over previous
#include <cuda_runtime.h>
#include <cstdint>

#define NNODES  50000
#define NPAD    50048      // 391 * 128
#define NEDGE   500000
#define DIM     128
#define DIM2    256
#define NLAYERS 5
#define NGRAPH  128

// ---------------- scratch (static device globals; zero-initialized) ----------------
__device__ float g_h [(size_t)NPAD * DIM];
__device__ float g_z [(size_t)NPAD * DIM];
__device__ float g_z1[(size_t)NPAD * DIM2];
__device__ float g_sum1[DIM2], g_sq1[DIM2];
__device__ float g_sum2[DIM ], g_sq2[DIM ];
__device__ int   g_cnt1, g_cnt2;
// pre-transposed [N][K], bf16-split (hi/lo), bf16x2-packed weights
__device__ uint32_t g_w1h[NLAYERS * DIM2 * (DIM / 2)];
__device__ uint32_t g_w1l[NLAYERS * DIM2 * (DIM / 2)];
__device__ uint32_t g_w2h[NLAYERS * DIM * (DIM2 / 2)];
__device__ uint32_t g_w2l[NLAYERS * DIM * (DIM2 / 2)];

// ---------------- PTX helpers (baseline features only) ----------------
__device__ __forceinline__ void red_add_v4(float* p, float4 v) {
    asm volatile("red.global.add.v4.f32 [%0], {%1, %2, %3, %4};"
                 :: "l"(p), "f"(v.x), "f"(v.y), "f"(v.z), "f"(v.w) : "memory");
}
__device__ __forceinline__ uint32_t bfpack(float v0, float v1) {
    uint32_t r;
    asm("cvt.rn.bf16x2.f32 %0, %1, %2;" : "=r"(r) : "f"(v1), "f"(v0));
    return r;
}
__device__ __forceinline__ uint32_t smem_u32(const void* p) {
    uint32_t a;
    asm("{ .reg .u64 t; cvta.to.shared.u64 t, %1; cvt.u32.u64 %0, t; }" : "=r"(a) : "l"(p));
    return a;
}
__device__ __forceinline__ void ldsm4(uint32_t r[4], uint32_t addr) {
    asm volatile("ldmatrix.sync.aligned.m8n8.x4.shared.b16 {%0,%1,%2,%3}, [%4];"
                 : "=r"(r[0]), "=r"(r[1]), "=r"(r[2]), "=r"(r[3]) : "r"(addr));
}
__device__ __forceinline__ void mma_bf16(float c[4], const uint32_t a[4],
                                         uint32_t b0, uint32_t b1) {
    asm volatile("mma.sync.aligned.m16n8k16.row.col.f32.bf16.bf16.f32 "
                 "{%0,%1,%2,%3}, {%4,%5,%6,%7}, {%8,%9}, {%0,%1,%2,%3};"
                 : "+f"(c[0]), "+f"(c[1]), "+f"(c[2]), "+f"(c[3])
                 : "r"(a[0]), "r"(a[1]), "r"(a[2]), "r"(a[3]), "r"(b0), "r"(b1));
}
__device__ __forceinline__ void cp16(uint32_t dst, const void* src) {
    asm volatile("cp.async.cg.shared.global [%0], [%1], 16;" :: "r"(dst), "l"(src));
}
#define CP_COMMIT() asm volatile("cp.async.commit_group;" ::: "memory")
#define CP_WAIT0()  asm volatile("cp.async.wait_group 0;" ::: "memory")

// ---------------- layer-0 init ----------------
__global__ void k_init(const int* __restrict__ x, const float* __restrict__ atom_emb,
                       float* __restrict__ out) {
    int i = blockIdx.x * blockDim.x + threadIdx.x;
    if (i < NGRAPH * DIM) out[i] = 0.f;
    if (i >= NNODES * 32) return;
    int n = i >> 5, c = (i & 31) * 4;
    int a = __ldg(x + n);
    float4 v = *(const float4*)(atom_emb + (size_t)a * DIM + c);
    *(float4*)(g_h + (size_t)n * DIM + c) = v;
    *(float4*)(g_z + (size_t)n * DIM + c) = v;
}

// ---------------- weight prep: transpose [N][K], bf16 hi/lo split, bf16x2 pack ----------------
__global__ void k_prep(const float* __restrict__ W1, const float* __restrict__ W2) {
    const int T1 = NLAYERS * DIM2 * (DIM / 2);
    const int T2 = NLAYERS * DIM * (DIM2 / 2);
    int i = blockIdx.x * blockDim.x + threadIdx.x;
    if (i < T1) {
        int l = i / (DIM2 * (DIM / 2)), r = i % (DIM2 * (DIM / 2));
        int n = r / (DIM / 2), w = r % (DIM / 2);
        const float* base = W1 + (size_t)l * DIM * DIM2;
        float v0 = base[(size_t)(2 * w) * DIM2 + n];
        float v1 = base[(size_t)(2 * w + 1) * DIM2 + n];
        uint32_t hp = bfpack(v0, v1);
        float f0 = __uint_as_float(hp << 16);
        float f1 = __uint_as_float(hp & 0xffff0000u);
        g_w1h[i] = hp;
        g_w1l[i] = bfpack(v0 - f0, v1 - f1);
    } else if (i < T1 + T2) {
        int j = i - T1;
        int l = j / (DIM * (DIM2 / 2)), r = j % (DIM * (DIM2 / 2));
        int n = r / (DIM2 / 2), w = r % (DIM2 / 2);
        const float* base = W2 + (size_t)l * DIM2 * DIM;
        float v0 = base[(size_t)(2 * w) * DIM + n];
        float v1 = base[(size_t)(2 * w + 1) * DIM + n];
        uint32_t hp = bfpack(v0, v1);
        float f0 = __uint_as_float(hp << 16);
        float f1 = __uint_as_float(hp & 0xffff0000u);
        g_w2h[j] = hp;
        g_w2l[j] = bfpack(v0 - f0, v1 - f1);
    }
}

// ---------------- message passing (8 edges/warp, MLP) ----------------
__global__ void k_scatter(const int* __restrict__ src, const int* __restrict__ dst,
                          const int* __restrict__ eattr, const float* __restrict__ bond_emb) {
    const int wid  = threadIdx.x >> 5;
    const int lane = threadIdx.x & 31;
    const int e0 = blockIdx.x * 64 + wid * 8;
    const int c4 = lane * 4;

    if (e0 + 8 <= NEDGE) {
        int s[8], d[8], a[8];
        #pragma unroll
        for (int j = 0; j < 8; j++) {
            s[j] = __ldg(src + e0 + j);
            d[j] = __ldg(dst + e0 + j);
            a[j] = __ldg(eattr + e0 + j);
        }
        float4 hv[8], ev[8];
        #pragma unroll
        for (int j = 0; j < 8; j++)
            hv[j] = *(const float4*)(g_h + (size_t)s[j] * DIM + c4);
        #pragma unroll
        for (int j = 0; j < 8; j++)
            ev[j] = *(const float4*)(bond_emb + (size_t)a[j] * DIM + c4);
        #pragma unroll
        for (int j = 0; j < 8; j++) {
            float4 m;
            m.x = fmaxf(hv[j].x + ev[j].x, 0.f);
            m.y = fmaxf(hv[j].y + ev[j].y, 0.f);
            m.z = fmaxf(hv[j].z + ev[j].z, 0.f);
            m.w = fmaxf(hv[j].w + ev[j].w, 0.f);
            red_add_v4(g_z + (size_t)d[j] * DIM + c4, m);
        }
    } else {
        for (int j = 0; j < 8; j++) {
            int e = e0 + j;
            if (e >= NEDGE) break;
            int s = __ldg(src + e), d = __ldg(dst + e), a = __ldg(eattr + e);
            float4 hv = *(const float4*)(g_h + (size_t)s * DIM + c4);
            float4 ev = *(const float4*)(bond_emb + (size_t)a * DIM + c4);
            float4 m;
            m.x = fmaxf(hv.x + ev.x, 0.f);
            m.y = fmaxf(hv.y + ev.y, 0.f);
            m.z = fmaxf(hv.z + ev.z, 0.f);
            m.w = fmaxf(hv.w + ev.w, 0.f);
            red_add_v4(g_z + (size_t)d * DIM + c4, m);
        }
    }
}

// ---------------- GEMM: 3x BF16-split mma.sync + cp.async pipelined staging ----------------
// CTA tile 128x128, 8 warps (2m x 4n), warp tile 64x32 = 4x4 m16n8k16 fragments (R13-proven).
// Chunk loop pipelined: cp.async for chunk c+1 (A fp32 -> staging buf; B pre-split ->
// double-buffered split tiles) issued BEFORE MMA(c); after MMA, wait + convert A.
// Dynamic smem (bytes from base):
//   AH0 @0  AH1 @10240  AL0 @20480  AL1 @30720  BH0 @40960  BH1 @51200
//   BL0 @61440  BL1 @71680  A32 @81920 (128 rows x 36 fl = 18432)   total 100352
#define GSMEM_BYTES 100352

template<int K, int NC, bool AFF>
__global__ void __launch_bounds__(256, 2)
k_gemm(const float* __restrict__ A,
       const uint32_t* __restrict__ Bh, const uint32_t* __restrict__ Bl,
       const float* __restrict__ bias,
       const float* __restrict__ sumA, const float* __restrict__ sqA,
       const float* __restrict__ gammaA, const float* __restrict__ betaA,
       int* __restrict__ cntA, int nCTA,
       float* __restrict__ C, float* __restrict__ gsum, float* __restrict__ gsq) {
    extern __shared__ uint32_t dyn[];
    __shared__ float sbias[128];
    __shared__ float saff[2 * 256];
    __shared__ int s_last;

    const uint32_t dynb = smem_u32(dyn);
    const uint32_t oAH[2] = {0u, 10240u};
    const uint32_t oAL[2] = {20480u, 30720u};
    const uint32_t oBH[2] = {40960u, 51200u};
    const uint32_t oBL[2] = {61440u, 71680u};
    const uint32_t oA32   = 81920u;

    const int tid  = threadIdx.x;
    const int lane = tid & 31, wid = tid >> 5;
    const int g = lane >> 2, tg = lane & 3;
    const int wm = wid >> 2, wn = wid & 3;
    const int mrow = wm * 64, ncol = wn * 32;
    const int bm0 = blockIdx.x * 128, bn0 = blockIdx.y * 128;

    if (tid < 128) sbias[tid] = bias[bn0 + tid];

    if (AFF) {
        if (tid < K) {
            const float invn = 1.0f / (float)NNODES;
            float mu  = sumA[tid] * invn;
            float var = fmaxf(sqA[tid] * invn - mu * mu, 0.f);
            float sc  = rsqrtf(var + 1e-5f) * gammaA[tid];
            saff[tid]     = sc;
            saff[K + tid] = betaA[tid] - mu * sc;
        }
        __syncthreads();
        if (tid == 0) {
            __threadfence();
            int old = atomicAdd(cntA, 1);
            s_last = (old == nCTA - 1);
        }
        __syncthreads();
        if (s_last) {
            if (tid < K) { ((float*)sumA)[tid] = 0.f; ((float*)sqA)[tid] = 0.f; }
            if (tid == 0) *cntA = 0;
        }
    }

    float acc[4][4][4];
    #pragma unroll
    for (int i = 0; i < 4; i++)
        #pragma unroll
        for (int j = 0; j < 4; j++)
            #pragma unroll
            for (int r = 0; r < 4; r++) acc[i][j][r] = 0.f;

    // staging mapping: 2 threads/row x 128 rows (both A and B tiles)
    const int s_row  = tid >> 1;
    const int s_half = tid & 1;
    const float*    Ab  = A  + (size_t)(bm0 + s_row) * K + s_half * 16;
    const uint32_t* Bhb = Bh + (size_t)(bn0 + s_row) * (K / 2) + s_half * 8;
    const uint32_t* Blb = Bl + (size_t)(bn0 + s_row) * (K / 2) + s_half * 8;
    const uint32_t a32b = (uint32_t)(s_row * 144 + s_half * 64);   // bytes (36-word rows)
    const uint32_t sofb = (uint32_t)(s_row * 80 + s_half * 32);    // bytes (20-word rows)

    const float* a32p = reinterpret_cast<const float*>(
        reinterpret_cast<const char*>(dyn) + oA32);

    const int CH = K / 32;

    // --- prologue: fetch + convert chunk 0 ---
    {
        cp16(dynb + oA32 + a32b,      Ab);
        cp16(dynb + oA32 + a32b + 16, Ab + 4);
        cp16(dynb + oA32 + a32b + 32, Ab + 8);
        cp16(dynb + oA32 + a32b + 48, Ab + 12);
        cp16(dynb + oBH[0] + sofb,      Bhb);
        cp16(dynb + oBH[0] + sofb + 16, Bhb + 4);
        cp16(dynb + oBL[0] + sofb,      Blb);
        cp16(dynb + oBL[0] + sofb + 16, Blb + 4);
        CP_COMMIT();
        CP_WAIT0();
        __syncthreads();
    }

    #pragma unroll 1
    for (int c = 0; c < CH; c++) {
        const int bf = c & 1;

        // ---- convert A chunk c: sA32 -> split tiles buf[bf] ----
        {
            const int kc = c * 32;
            float v[16];
            *(float4*)&v[0]  = *(const float4*)(a32p + s_row * 36 + s_half * 16);
            *(float4*)&v[4]  = *(const float4*)(a32p + s_row * 36 + s_half * 16 + 4);
            *(float4*)&v[8]  = *(const float4*)(a32p + s_row * 36 + s_half * 16 + 8);
            *(float4*)&v[12] = *(const float4*)(a32p + s_row * 36 + s_half * 16 + 12);
            if (AFF) {
                const float* sc = saff + kc + s_half * 16;
                const float* sh = sc + K;
                #pragma unroll
                for (int j = 0; j < 16; j++)
                    v[j] = fmaxf(fmaf(v[j], sc[j], sh[j]), 0.f);
            }
            uint32_t hw[8], lw[8];
            #pragma unroll
            for (int p = 0; p < 8; p++) {
                float v0 = v[2 * p], v1 = v[2 * p + 1];
                uint32_t hp = bfpack(v0, v1);
                float f0 = __uint_as_float(hp << 16);
                float f1 = __uint_as_float(hp & 0xffff0000u);
                hw[p] = hp;
                lw[p] = bfpack(v0 - f0, v1 - f1);
            }
            uint32_t* ahp = reinterpret_cast<uint32_t*>(
                reinterpret_cast<char*>(dyn) + oAH[bf] + sofb);
            uint32_t* alp = reinterpret_cast<uint32_t*>(
                reinterpret_cast<char*>(dyn) + oAL[bf] + sofb);
            *(uint4*)(ahp)     = *(uint4*)&hw[0];
            *(uint4*)(ahp + 4) = *(uint4*)&hw[4];
            *(uint4*)(alp)     = *(uint4*)&lw[0];
            *(uint4*)(alp + 4) = *(uint4*)&lw[4];
        }
        __syncthreads();   // split tiles buf[bf] ready; sA32 free for reuse

        // ---- prefetch chunk c+1 (A fp32 -> sA32; B -> split buf[bf^1]) ----
        const bool nxt = (c + 1 < CH);
        if (nxt) {
            const int kc1 = (c + 1) * 32;
            cp16(dynb + oA32 + a32b,      Ab + kc1);
            cp16(dynb + oA32 + a32b + 16, Ab + kc1 + 4);
            cp16(dynb + oA32 + a32b + 32, Ab + kc1 + 8);
            cp16(dynb + oA32 + a32b + 48, Ab + kc1 + 12);
            cp16(dynb + oBH[bf ^ 1] + sofb,      Bhb + kc1 / 2);
            cp16(dynb + oBH[bf ^ 1] + sofb + 16, Bhb + kc1 / 2 + 4);
            cp16(dynb + oBL[bf ^ 1] + sofb,      Blb + kc1 / 2);
            cp16(dynb + oBL[bf ^ 1] + sofb + 16, Blb + kc1 / 2 + 4);
            CP_COMMIT();
        }

        // ---- MMA on chunk c (split tiles buf[bf]) ----
        {
            const uint32_t aBh = dynb + oAH[bf], aBl = dynb + oAL[bf];
            const uint32_t bBh = dynb + oBH[bf], bBl = dynb + oBL[bf];
            #pragma unroll
            for (int k16 = 0; k16 < 2; k16++) {
                const uint32_t lrow = (uint32_t)((lane & 7) + (((lane >> 3) & 1) << 3));
                const uint32_t lcol = (uint32_t)(((lane >> 4) & 1) * 4 + k16 * 8);
                uint32_t bh[2][4], bl[2][4];
                #pragma unroll
                for (int jp = 0; jp < 2; jp++) {
                    uint32_t ba = ((uint32_t)(ncol + jp * 16) + lrow) * 80u + lcol * 4u;
                    ldsm4(bh[jp], bBh + ba);
                    ldsm4(bl[jp], bBl + ba);
                }
                #pragma unroll
                for (int i = 0; i < 4; i++) {
                    uint32_t ra = ((uint32_t)(mrow + i * 16) + lrow) * 80u + lcol * 4u;
                    uint32_t ah[4], al[4];
                    ldsm4(ah, aBh + ra);
                    ldsm4(al, aBl + ra);
                    #pragma unroll
                    for (int j = 0; j < 4; j++) {
                        const int jp = j >> 1, od = j & 1;
                        mma_bf16(acc[i][j], ah, bh[jp][od], bh[jp][2 + od]);
                        mma_bf16(acc[i][j], ah, bl[jp][od], bl[jp][2 + od]);
                        mma_bf16(acc[i][j], al, bh[jp][od], bh[jp][2 + od]);
                    }
                }
            }
        }

        if (nxt) {
            CP_WAIT0();
            __syncthreads();   // prefetched data landed; MMA(c) reads done for all warps
        }
    }

    // ---- epilogue: bias, store, masked column stats (R13-proven mapping) ----
    float ps[4][2], pq[4][2];
    #pragma unroll
    for (int j = 0; j < 4; j++) { ps[j][0] = ps[j][1] = pq[j][0] = pq[j][1] = 0.f; }

    #pragma unroll
    for (int i = 0; i < 4; i++) {
        int r0 = bm0 + mrow + i * 16 + g;
        int r1 = r0 + 8;
        #pragma unroll
        for (int j = 0; j < 4; j++) {
            int lc = ncol + j * 8 + 2 * tg;
            float b0 = sbias[lc], b1 = sbias[lc + 1];
            float v0 = acc[i][j][0] + b0, v1 = acc[i][j][1] + b1;
            float v2 = acc[i][j][2] + b0, v3 = acc[i][j][3] + b1;
            *(float2*)(C + (size_t)r0 * NC + bn0 + lc) = make_float2(v0, v1);
            *(float2*)(C + (size_t)r1 * NC + bn0 + lc) = make_float2(v2, v3);
            if (r0 < NNODES) {
                ps[j][0] += v0; pq[j][0] += v0 * v0;
                ps[j][1] += v1; pq[j][1] += v1 * v1;
            }
            if (r1 < NNODES) {
                ps[j][0] += v2; pq[j][0] += v2 * v2;
                ps[j][1] += v3; pq[j][1] += v3 * v3;
            }
        }
    }
    #pragma unroll
    for (int j = 0; j < 4; j++)
        #pragma unroll
        for (int t2 = 0; t2 < 2; t2++) {
            float s = ps[j][t2], q = pq[j][t2];
            s += __shfl_xor_sync(0xFFFFFFFFu, s, 4);
            q += __shfl_xor_sync(0xFFFFFFFFu, q, 4);
            s += __shfl_xor_sync(0xFFFFFFFFu, s, 8);
            q += __shfl_xor_sync(0xFFFFFFFFu, q, 8);
            s += __shfl_xor_sync(0xFFFFFFFFu, s, 16);
            q += __shfl_xor_sync(0xFFFFFFFFu, q, 16);
            if (lane < 4) {
                int col = bn0 + ncol + j * 8 + 2 * tg + t2;
                atomicAdd(gsum + col, s);
                atomicAdd(gsq  + col, q);
            }
        }
}

// ---------------- apply BN2 (+optional ReLU): h = bn(z2); z = h ----------------
__global__ void k_bnapply(const float* __restrict__ gamma, const float* __restrict__ beta,
                          int relu, int nBLK) {
    __shared__ float saff[2 * DIM];
    __shared__ int s_last;
    int tid = threadIdx.x;
    if (tid < DIM) {
        const float invn = 1.0f / (float)NNODES;
        float mu  = g_sum2[tid] * invn;
        float var = fmaxf(g_sq2[tid] * invn - mu * mu, 0.f);
        float sc  = rsqrtf(var + 1e-5f) * gamma[tid];
        saff[tid]       = sc;
        saff[DIM + tid] = beta[tid] - mu * sc;
    }
    __syncthreads();
    if (tid == 0) {
        __threadfence();
        int old = atomicAdd(&g_cnt2, 1);
        s_last = (old == nBLK - 1);
    }
    __syncthreads();
    if (s_last) {
        if (tid < DIM) { g_sum2[tid] = 0.f; g_sq2[tid] = 0.f; }
        if (tid == 0) g_cnt2 = 0;
    }

    int i = blockIdx.x * blockDim.x + tid;
    if (i >= NNODES * 32) return;
    int n = i >> 5, c = (i & 31) * 4;
    float4 v  = *(const float4*)(g_z + (size_t)n * DIM + c);
    float4 sc = *(const float4*)(saff + c);
    float4 sh = *(const float4*)(saff + DIM + c);
    v.x = fmaf(v.x, sc.x, sh.x);
    v.y = fmaf(v.y, sc.y, sh.y);
    v.z = fmaf(v.z, sc.z, sh.z);
    v.w = fmaf(v.w, sc.w, sh.w);
    if (relu) {
        v.x = fmaxf(v.x, 0.f); v.y = fmaxf(v.y, 0.f);
        v.z = fmaxf(v.z, 0.f); v.w = fmaxf(v.w, 0.f);
    }
    *(float4*)(g_h + (size_t)n * DIM + c) = v;
    *(float4*)(g_z + (size_t)n * DIM + c) = v;
}

__global__ void k_pool(const int* __restrict__ batch, float* __restrict__ out) {
    int i = blockIdx.x * blockDim.x + threadIdx.x;
    if (i >= NNODES * 32) return;
    int n = i >> 5, c = (i & 31) * 4;
    float4 v = *(const float4*)(g_h + (size_t)n * DIM + c);
    *(float4*)(out + (size_t)NGRAPH * DIM + (size_t)n * DIM + c) = v;
    int b = __ldg(batch + n);
    red_add_v4(out + (size_t)b * DIM + c, v);
}

// ---------------- launch ----------------
extern "C" void kernel_launch(void* const* d_in, const int* in_sizes, int n_in,
                              void* d_out, int out_size) {
    const int*   batch    = (const int*)  d_in[0];
    const int*   x        = (const int*)  d_in[1];
    const int*   eidx     = (const int*)  d_in[2];
    const int*   eattr    = (const int*)  d_in[3];
    const float* atom_emb = (const float*)d_in[4];
    const float* bond_emb = (const float*)d_in[5];
    const float* W1       = (const float*)d_in[6];
    const float* b1       = (const float*)d_in[7];
    const float* g1       = (const float*)d_in[8];
    const float* be1      = (const float*)d_in[9];
    const float* W2       = (const float*)d_in[10];
    const float* b2       = (const float*)d_in[11];
    const float* gbn      = (const float*)d_in[12];
    const float* bbn      = (const float*)d_in[13];
    float* out = (float*)d_out;

    float *p_z, *p_z1, *p_sum1, *p_sq1, *p_sum2, *p_sq2;
    int *p_cnt1;
    uint32_t *p_w1h, *p_w1l, *p_w2h, *p_w2l;
    cudaGetSymbolAddress((void**)&p_z,    g_z);
    cudaGetSymbolAddress((void**)&p_z1,   g_z1);
    cudaGetSymbolAddress((void**)&p_sum1, g_sum1);
    cudaGetSymbolAddress((void**)&p_sq1,  g_sq1);
    cudaGetSymbolAddress((void**)&p_sum2, g_sum2);
    cudaGetSymbolAddress((void**)&p_sq2,  g_sq2);
    cudaGetSymbolAddress((void**)&p_cnt1, g_cnt1);
    cudaGetSymbolAddress((void**)&p_w1h,  g_w1h);
    cudaGetSymbolAddress((void**)&p_w1l,  g_w1l);
    cudaGetSymbolAddress((void**)&p_w2h,  g_w2h);
    cudaGetSymbolAddress((void**)&p_w2l,  g_w2l);

    cudaFuncSetAttribute(k_gemm<DIM,  DIM2, false>,
                         cudaFuncAttributeMaxDynamicSharedMemorySize, GSMEM_BYTES);
    cudaFuncSetAttribute(k_gemm<DIM2, DIM,  true>,
                         cudaFuncAttributeMaxDynamicSharedMemorySize, GSMEM_BYTES);

    const int* src = eidx;
    const int* dst = eidx + NEDGE;
    const int ELEM_GRID = (NNODES * 32 + 255) / 256;
    const int G2_CTAS   = NPAD / 128;   // 391 (GEMM2 grid, y=1)
    const int PREP_TOT  = NLAYERS * DIM2 * (DIM / 2) + NLAYERS * DIM * (DIM2 / 2);

    k_init<<<ELEM_GRID, 256>>>(x, atom_emb, out);
    k_prep<<<(PREP_TOT + 255) / 256, 256>>>(W1, W2);

    for (int i = 0; i < NLAYERS; i++) {
        k_scatter<<<(NEDGE + 63) / 64, 256>>>(src, dst, eattr, bond_emb);
        k_gemm<DIM, DIM2, false><<<dim3(NPAD / 128, DIM2 / 128), 256, GSMEM_BYTES>>>(
            p_z, p_w1h + (size_t)i * DIM2 * (DIM / 2), p_w1l + (size_t)i * DIM2 * (DIM / 2),
            b1 + (size_t)i * DIM2,
            nullptr, nullptr, nullptr, nullptr, nullptr, 0,
            p_z1, p_sum1, p_sq1);
        k_gemm<DIM2, DIM, true><<<dim3(NPAD / 128, 1), 256, GSMEM_BYTES>>>(
            p_z1, p_w2h + (size_t)i * DIM * (DIM2 / 2), p_w2l + (size_t)i * DIM * (DIM2 / 2),
            b2 + (size_t)i * DIM,
            p_sum1, p_sq1, g1 + (size_t)i * DIM2, be1 + (size_t)i * DIM2,
            p_cnt1, G2_CTAS,
            p_z, p_sum2, p_sq2);
        k_bnapply<<<ELEM_GRID, 256>>>(gbn + (size_t)i * DIM, bbn + (size_t)i * DIM,
                                      i < NLAYERS - 1 ? 1 : 0, ELEM_GRID);
    }

    k_pool<<<ELEM_GRID, 256>>>(batch, out);
}